// round 9
// baseline (speedup 1.0000x reference)
#include <cuda_runtime.h>

#define SC   25     // (LMAX+1)^2
#define RBC  12
#define RAC  11
#define DC   64
#define NP   15     // (l, m>=0) pairs
#define TPB  128

typedef unsigned long long u64;

// ---------- packed f32x2 helpers ----------
__device__ __forceinline__ u64 pk(float lo, float hi) {
    u64 r; asm("mov.b64 %0, {%1,%2};" : "=l"(r) : "f"(lo), "f"(hi)); return r;
}
__device__ __forceinline__ void unpk(u64 v, float& lo, float& hi) {
    asm("mov.b64 {%0,%1}, %2;" : "=f"(lo), "=f"(hi) : "l"(v));
}
__device__ __forceinline__ u64 fma2(u64 a, u64 b, u64 c) {
    u64 d; asm("fma.rn.f32x2 %0, %1, %2, %3;" : "=l"(d) : "l"(a), "l"(b), "l"(c)); return d;
}

// (l,m) pair tables, p = l(l+1)/2 + m, m = 0..l (folded at compile time in unrolled loops)
static __device__ const int c_ip[NP] = {0, 2,3, 6,7,8, 12,13,14,15, 20,21,22,23,24};
static __device__ const int c_in[NP] = {0, 2,1, 6,5,4, 12,11,10, 9, 20,19,18,17,16};
static __device__ const int c_m [NP] = {0, 0,1, 0,1,2,  0, 1, 2, 3,  0, 1, 2, 3, 4};

__global__ void __launch_bounds__(TPB, 3)
gtp_main(const float* __restrict__ x1, const float* __restrict__ x2,
         const float* __restrict__ W1, const float* __restrict__ W2,
         const float* __restrict__ Y,  const float* __restrict__ Yw,
         float* __restrict__ out, int nrows)
{
    __shared__ __align__(16) u64 sW[DC * 26];      // (W1[d,s], W2[d,s]) pairs + pad; 13.3KB
    __shared__ __align__(16) float4 sBuf[1024];    // input staging, later output staging; 16KB
    __shared__ __align__(16) u64 sP  [RBC * 16];   // (P,P)
    __shared__ __align__(16) u64 sPw [RBC * 16];   // (P*qw, P*qw)
    __shared__ __align__(16) u64 sAngJ[6 * 16];    // per mirror-point j: C0..C4,S1..S4,M0..M4,pad

    const int tid = threadIdx.x;
    const float SQ2  = 1.41421356237309505f;
    const float ISQ2 = 0.70710678118654752f;

    // ---- build tables from W / Y / Yw (exact extraction, no trig) ----
    for (int k = tid; k < DC * 26; k += TPB) {
        int d = k / 26, s = k % 26;
        sW[k] = (s < SC) ? pk(W1[d * SC + s], W2[d * SC + s]) : 0ull;
    }

    for (int t = tid; t < RBC * 16; t += TPB) {
        int b = t / 16, p = t % 16;
        if (p == 15) { sP[t] = 0ull; sPw[t] = 0ull; }
        else {
            int l = (p >= 10) ? 4 : (p >= 6) ? 3 : (p >= 3) ? 2 : (p >= 1) ? 1 : 0;
            int m = p - l * (l + 1) / 2;
            int ip = l * l + l + m;
            float y0 = Y[(b * RAC) * SC + ip];                 // a=0: ang=1 (m=0) or sqrt2 (m>0)
            float P  = (m > 0) ? y0 * ISQ2 : y0;
            float qw = Yw[(b * RAC) * SC] / Y[(b * RAC) * SC]; // Y[b,0,0] > 0, const over a
            sP [t] = pk(P, P);
            float pw = P * qw;
            sPw[t] = pk(pw, pw);
        }
    }

    // angle table per half-grid point j (a=6..10 mirror a=5..1):
    // slots [0..4]=(c_m,c_m) m=0..4, [5..8]=(s_m,s_m) m=1..4, [9..13]=(c_m,s_m) m=0..4, [14..15]=pad
    for (int t = tid; t < 6 * 16; t += TPB) {
        int j = t / 16, k = t % 16;
        if (k >= 14) { sAngJ[t] = 0ull; continue; }
        int m = (k <= 4) ? k : (k <= 8) ? (k - 4) : (k - 9);
        float cm, sm;
        if (m == 0) { cm = 1.0f; sm = 0.0f; }
        else {
            const int b0 = RBC / 2;                            // mid Gauss node, P[m,m] != 0
            int ip = m * m + 2 * m, in_ = m * m;
            float den = Y[(b0 * RAC) * SC + ip];               // sqrt2 * P[m,m](x_b0)
            cm = SQ2 * Y[(b0 * RAC + j) * SC + ip ] / den;
            sm = SQ2 * Y[(b0 * RAC + j) * SC + in_] / den;
        }
        sAngJ[t] = (k <= 4) ? pk(cm, cm) : (k <= 8) ? pk(sm, sm) : pk(cm, sm);
    }

    // ================= phase 1: projection, (x1,x2) lane packing =================
    // cc[s] = (c1[s], c2[s]) = sum_d (x1[d], x2[d]) * (W1[d,s], W2[d,s])
    u64 cc[SC];
    #pragma unroll
    for (int s = 0; s < SC; s++) cc[s] = 0ull;

    const long long rowsLeft = (long long)nrows - (long long)blockIdx.x * TPB;
    const long long base = (long long)blockIdx.x * TPB * DC;

    #pragma unroll 1
    for (int q = 0; q < 4; q++) {
        __syncthreads();
        // coalesced: 128 rows x 16 floats per input for this d-quarter
        #pragma unroll
        for (int i = 0; i < 4; i++) {
            int k = i * TPB + tid;            // 0..511
            int row = k >> 2, c4 = k & 3;
            long long rg = (row < rowsLeft) ? row : (rowsLeft - 1);
            long long g = base + rg * DC + q * 16 + c4 * 4;
            int idx = c4 * 128 + ((row + 2 * c4) & 127);   // swizzle: conflict-free STS/LDS
            sBuf[idx]       = *(const float4*)(x1 + g);
            sBuf[512 + idx] = *(const float4*)(x2 + g);
        }
        __syncthreads();
        #pragma unroll
        for (int j = 0; j < 4; j++) {
            int idx = j * 128 + ((tid + 2 * j) & 127);
            float4 A4 = sBuf[idx];
            float4 B4 = sBuf[512 + idx];
            float av[4] = {A4.x, A4.y, A4.z, A4.w};
            float bv[4] = {B4.x, B4.y, B4.z, B4.w};
            #pragma unroll
            for (int w = 0; w < 4; w++) {
                int d = q * 16 + j * 4 + w;
                u64 xd = pk(av[w], bv[w]);               // (x1[d], x2[d])
                const ulonglong2* Wd = (const ulonglong2*)&sW[d * 26];  // d*26 even -> aligned
                #pragma unroll
                for (int ss = 0; ss < 13; ss++) {
                    ulonglong2 w2 = Wd[ss];
                    cc[2 * ss] = fma2(xd, w2.x, cc[2 * ss]);
                    if (2 * ss + 1 < SC) cc[2 * ss + 1] = fma2(xd, w2.y, cc[2 * ss + 1]);
                }
            }
        }
    }

    // ================= phase 2: sphere (consumes (c1,c2) packing natively) ==========
    u64 accp[NP];
    #pragma unroll
    for (int p = 0; p < NP; p++) accp[p] = 0ull;

    #pragma unroll 1
    for (int b = 0; b < RBC; b++) {
        const ulonglong2* Pv  = (const ulonglong2*)&sP [b * 16];
        const ulonglong2* Pwv = (const ulonglong2*)&sPw[b * 16];

        // F[4+m'] = (F1[m'], F2[m']) = sum_l cc[idx(l,m')] * P[l,|m'|]
        u64 F[9];
        #pragma unroll
        for (int i = 0; i < 9; i++) F[i] = 0ull;
        #pragma unroll
        for (int pp = 0; pp < 8; pp++) {
            ulonglong2 P2 = Pv[pp];
            const int p0 = 2 * pp, p1 = 2 * pp + 1;
            F[4 + c_m[p0]] = fma2(cc[c_ip[p0]], P2.x, F[4 + c_m[p0]]);
            if (c_m[p0] > 0) F[4 - c_m[p0]] = fma2(cc[c_in[p0]], P2.x, F[4 - c_m[p0]]);
            if (p1 < NP) {
                F[4 + c_m[p1]] = fma2(cc[c_ip[p1]], P2.y, F[4 + c_m[p1]]);
                if (c_m[p1] > 0) F[4 - c_m[p1]] = fma2(cc[c_in[p1]], P2.y, F[4 - c_m[p1]]);
            }
        }

        u64 H[5];   // H[m] = (H+_m, H-_m)
        #pragma unroll
        for (int m = 0; m < 5; m++) H[m] = 0ull;

        #pragma unroll
        for (int j = 0; j < 6; j++) {
            const ulonglong2* Aj = (const ulonglong2*)&sAngJ[j * 16];
            ulonglong2 e0 = Aj[0], e1 = Aj[1], e2 = Aj[2], e3 = Aj[3],
                       e4 = Aj[4], e5 = Aj[5], e6 = Aj[6];
            u64 C0 = e0.x, C1 = e0.y, C2 = e1.x, C3 = e1.y, C4 = e2.x;
            u64 S1 = e2.y, S2 = e3.x, S3 = e3.y, S4 = e4.x;
            u64 M0 = e4.y, M1 = e5.x, M2 = e5.y, M3 = e6.x, M4 = e6.y;

            // even part: sum_{m>=0} F[4+m]*c_m ; odd part: sum_{m>0} F[4-m]*s_m
            u64 E = 0ull;
            E = fma2(F[4], C0, E);
            E = fma2(F[5], C1, E);
            E = fma2(F[6], C2, E);
            E = fma2(F[7], C3, E);
            E = fma2(F[8], C4, E);

            u64 hp;
            if (j == 0) {                          // a = 0: self-mirror, odd part = 0
                float e1f, e2f; unpk(E, e1f, e2f);
                float ha = e1f * e2f;
                hp = pk(ha, ha);
            } else {
                u64 O = 0ull;
                O = fma2(F[3], S1, O);
                O = fma2(F[2], S2, O);
                O = fma2(F[1], S3, O);
                O = fma2(F[0], S4, O);
                float e1f, e2f, o1f, o2f;
                unpk(E, e1f, e2f); unpk(O, o1f, o2f);
                float ha = (e1f + o1f) * (e2f + o2f);   // grid product at a = j
                float hb = (e1f - o1f) * (e2f - o2f);   // grid product at a = 11 - j
                hp = pk(ha + hb, ha - hb);              // (cos lane, sin lane)
            }
            H[0] = fma2(hp, M0, H[0]);
            H[1] = fma2(hp, M1, H[1]);
            H[2] = fma2(hp, M2, H[2]);
            H[3] = fma2(hp, M3, H[3]);
            H[4] = fma2(hp, M4, H[4]);
        }

        #pragma unroll
        for (int pp = 0; pp < 8; pp++) {
            ulonglong2 Pw2 = Pwv[pp];
            const int p0 = 2 * pp, p1 = 2 * pp + 1;
            accp[p0] = fma2(H[c_m[p0]], Pw2.x, accp[p0]);
            if (p1 < NP) accp[p1] = fma2(H[c_m[p1]], Pw2.y, accp[p1]);
        }
    }

    // ================= phase 3: output (stage in shared, coalesced stores) ==========
    __syncthreads();                      // sBuf dead as input staging everywhere in CTA
    float* sOut = (float*)sBuf;
    #pragma unroll
    for (int p = 0; p < NP; p++) {
        float lo, hi; unpk(accp[p], lo, hi);
        sOut[tid * SC + c_ip[p]] = lo;
        if (c_m[p] > 0) sOut[tid * SC + c_in[p]] = hi;
    }
    __syncthreads();
    const float4* sOv = (const float4*)sOut;
    const long long obase4 = (long long)blockIdx.x * TPB * SC / 4;   // CTA tile: 800 float4
    const long long otot4  = (long long)nrows * SC / 4;
    float4* og = (float4*)out;
    #pragma unroll
    for (int k = tid; k < TPB * SC / 4; k += TPB) {
        if (obase4 + k < otot4) og[obase4 + k] = sOv[k];
    }
}

extern "C" void kernel_launch(void* const* d_in, const int* in_sizes, int n_in,
                              void* d_out, int out_size) {
    const float* x1 = (const float*)d_in[0];
    const float* x2 = (const float*)d_in[1];
    const float* W1 = (const float*)d_in[2];
    const float* W2 = (const float*)d_in[3];
    const float* Y  = (const float*)d_in[4];
    const float* Yw = (const float*)d_in[5];
    float* out = (float*)d_out;

    const int nrows = in_sizes[0] / DC;            // 131072
    const int grid  = (nrows + TPB - 1) / TPB;     // 1024

    gtp_main<<<grid, TPB>>>(x1, x2, W1, W2, Y, Yw, out, nrows);
}

// round 10
// speedup vs baseline: 2.0073x; 2.0073x over previous
#include <cuda_runtime.h>

#define SC   25     // (LMAX+1)^2
#define RBC  12
#define RAC  11
#define DC   64
#define NP   15     // (l, m>=0) pairs
#define TPB  128

typedef unsigned long long u64;

// ---------- packed f32x2 helpers ----------
__device__ __forceinline__ u64 pk(float lo, float hi) {
    u64 r; asm("mov.b64 %0, {%1,%2};" : "=l"(r) : "f"(lo), "f"(hi)); return r;
}
__device__ __forceinline__ void unpk(u64 v, float& lo, float& hi) {
    asm("mov.b64 {%0,%1}, %2;" : "=f"(lo), "=f"(hi) : "l"(v));
}
__device__ __forceinline__ u64 fma2(u64 a, u64 b, u64 c) {
    u64 d; asm("fma.rn.f32x2 %0, %1, %2, %3;" : "=l"(d) : "l"(a), "l"(b), "l"(c)); return d;
}

// (l,m) pair tables, p = l(l+1)/2 + m, m = 0..l (folded at compile time in unrolled loops)
static __device__ const int c_ip[NP] = {0, 2,3, 6,7,8, 12,13,14,15, 20,21,22,23,24};
static __device__ const int c_in[NP] = {0, 2,1, 6,5,4, 12,11,10, 9, 20,19,18,17,16};
static __device__ const int c_m [NP] = {0, 0,1, 0,1,2,  0, 1, 2, 3,  0, 1, 2, 3, 4};

__global__ void __launch_bounds__(TPB, 3)
gtp_main(const float* __restrict__ x1, const float* __restrict__ x2,
         const float* __restrict__ W1, const float* __restrict__ W2,
         const float* __restrict__ Y,  const float* __restrict__ Yw,
         float* __restrict__ out, int nrows)
{
    __shared__ __align__(16) ulonglong2 sW[DC * 16];  // {W1(+m,-m), W2(+m,-m)} pairs, 16KB
    __shared__ __align__(16) float4 sBuf[2][512];     // double-buffered staging (8KB each)
    __shared__ __align__(16) u64 sP [RBC * 16];       // (P,P)
    __shared__ __align__(16) u64 sPw[RBC * 16];       // (P*qw, P*qw)
    __shared__ __align__(16) u64 sAng[6 * 6];         // alpha half-grid j=0..5: m=0..4 pairs + pad

    const int tid = threadIdx.x;
    const float SQ2  = 1.41421356237309505f;
    const float ISQ2 = 0.70710678118654752f;

    // ---- build tables from W / Y / Yw (exact extraction, no trig) ----
    for (int k = tid; k < DC * NP; k += TPB) {
        int d = k / NP, p = k % NP;
        int l = (p >= 10) ? 4 : (p >= 6) ? 3 : (p >= 3) ? 2 : (p >= 1) ? 1 : 0;
        int m = p - l * (l + 1) / 2;
        int ip = l * l + l + m, in_ = ip - 2 * m;
        ulonglong2 w;
        w.x = pk(W1[d * SC + ip], W1[d * SC + in_]);
        w.y = pk(W2[d * SC + ip], W2[d * SC + in_]);
        sW[d * 16 + p] = w;
    }
    for (int d = tid; d < DC; d += TPB) { ulonglong2 z; z.x = 0; z.y = 0; sW[d * 16 + 15] = z; }

    for (int t = tid; t < RBC * 16; t += TPB) {
        int b = t / 16, p = t % 16;
        if (p == 15) { sP[t] = 0ull; sPw[t] = 0ull; }
        else {
            int l = (p >= 10) ? 4 : (p >= 6) ? 3 : (p >= 3) ? 2 : (p >= 1) ? 1 : 0;
            int m = p - l * (l + 1) / 2;
            int ip = l * l + l + m;
            float y0 = Y[(b * RAC) * SC + ip];                 // a=0: ang=1 (m=0) or sqrt2 (m>0)
            float P  = (m > 0) ? y0 * ISQ2 : y0;
            float qw = Yw[(b * RAC) * SC] / Y[(b * RAC) * SC]; // Y[b,0,0] > 0, const over a
            sP [t] = pk(P, P);
            float pw = P * qw;
            sPw[t] = pk(pw, pw);
        }
    }

    // alpha half-grid: j=0..5 (points a=6..10 are mirrors of a=5..1)
    for (int t = tid; t < 6 * 6; t += TPB) {
        int a = t / 6, m = t % 6;
        if (m == 5)      sAng[t] = 0ull;
        else if (m == 0) sAng[t] = pk(1.0f, 0.0f);
        else {
            const int b0 = RBC / 2;                            // mid Gauss node, P[m,m] != 0
            int ip = m * m + 2 * m, in_ = m * m;
            float den = Y[(b0 * RAC) * SC + ip];               // sqrt2 * P[m,m](x_b0)
            float ac2 = SQ2 * Y[(b0 * RAC + a) * SC + ip ] / den;
            float as2 = SQ2 * Y[(b0 * RAC + a) * SC + in_] / den;
            sAng[t] = pk(ac2, as2);
        }
    }

    // ---- projection: double-buffered 8-float chunks (software pipeline) ----
    u64 c1p[NP], c2p[NP];
    #pragma unroll
    for (int p = 0; p < NP; p++) { c1p[p] = 0ull; c2p[p] = 0ull; }

    const long long rowsLeft = (long long)nrows - (long long)blockIdx.x * TPB;
    const long long base = (long long)blockIdx.x * TPB * DC;

    // chunk c covers d = c*8 .. c*8+7.  Per chunk per input: 128 rows x 2 float4.
    // load distribution: 2 float4 per thread per input.
    {
        // prologue: load chunk 0 into buffer 0
        #pragma unroll
        for (int i = 0; i < 2; i++) {
            int k = i * TPB + tid;            // 0..255
            int row = k >> 1, c4 = k & 1;
            long long rg = (row < rowsLeft) ? row : (rowsLeft - 1);
            long long g = base + rg * DC + c4 * 4;
            int idx = c4 * 128 + ((row + 2 * c4) & 127);
            sBuf[0][idx]       = *(const float4*)(x1 + g);
            sBuf[0][256 + idx] = *(const float4*)(x2 + g);
        }
    }
    __syncthreads();

    #pragma unroll 1
    for (int c = 0; c < 8; c++) {
        // issue loads for chunk c+1 into the other buffer (overlaps with consume below)
        if (c < 7) {
            const int nb = (c + 1) & 1;
            #pragma unroll
            for (int i = 0; i < 2; i++) {
                int k = i * TPB + tid;
                int row = k >> 1, c4 = k & 1;
                long long rg = (row < rowsLeft) ? row : (rowsLeft - 1);
                long long g = base + rg * DC + (c + 1) * 8 + c4 * 4;
                int idx = c4 * 128 + ((row + 2 * c4) & 127);
                sBuf[nb][idx]       = *(const float4*)(x1 + g);
                sBuf[nb][256 + idx] = *(const float4*)(x2 + g);
            }
        }
        // consume chunk c
        const int cb = c & 1;
        #pragma unroll
        for (int j = 0; j < 2; j++) {
            int idx = j * 128 + ((tid + 2 * j) & 127);
            float4 A = sBuf[cb][idx];
            float4 B = sBuf[cb][256 + idx];
            float av[4] = {A.x, A.y, A.z, A.w};
            float bv[4] = {B.x, B.y, B.z, B.w};
            #pragma unroll
            for (int w = 0; w < 4; w++) {
                int d = c * 8 + j * 4 + w;
                u64 xd1 = pk(av[w], av[w]);
                u64 xd2 = pk(bv[w], bv[w]);
                const ulonglong2* Wd = &sW[d * 16];
                #pragma unroll
                for (int p = 0; p < NP; p++) {
                    ulonglong2 W = Wd[p];
                    c1p[p] = fma2(xd1, W.x, c1p[p]);
                    c2p[p] = fma2(xd2, W.y, c2p[p]);
                }
            }
        }
        __syncthreads();
    }

    // ---- sphere: per beta node, F -> mirrored alpha grid -> H -> back-project ----
    u64 accp[NP];
    #pragma unroll
    for (int p = 0; p < NP; p++) accp[p] = 0ull;

    #pragma unroll 1
    for (int b = 0; b < RBC; b++) {
        const ulonglong2* Pv  = (const ulonglong2*)&sP [b * 16];
        const ulonglong2* Pwv = (const ulonglong2*)&sPw[b * 16];

        u64 F1[5], F2[5];
        #pragma unroll
        for (int m = 0; m < 5; m++) { F1[m] = 0ull; F2[m] = 0ull; }
        #pragma unroll
        for (int pp = 0; pp < 8; pp++) {
            ulonglong2 P2 = Pv[pp];
            const int p0 = 2 * pp, p1 = 2 * pp + 1;
            F1[c_m[p0]] = fma2(c1p[p0], P2.x, F1[c_m[p0]]);
            F2[c_m[p0]] = fma2(c2p[p0], P2.x, F2[c_m[p0]]);
            if (p1 < NP) {
                F1[c_m[p1]] = fma2(c1p[p1], P2.y, F1[c_m[p1]]);
                F2[c_m[p1]] = fma2(c2p[p1], P2.y, F2[c_m[p1]]);
            }
        }

        u64 H[5];
        #pragma unroll
        for (int m = 0; m < 5; m++) H[m] = 0ull;

        // alpha half-grid: chain lanes = (cos-part, sin-part); g(a)=lo+hi, g(11-a)=lo-hi
        #pragma unroll
        for (int j = 0; j < 6; j++) {
            const ulonglong2* Av = (const ulonglong2*)&sAng[j * 6];
            ulonglong2 A0 = Av[0], A1 = Av[1], A2 = Av[2];
            u64 am0 = A0.x, am1 = A0.y, am2 = A1.x, am3 = A1.y, am4 = A2.x;

            u64 g1 = 0ull, g2 = 0ull;
            g1 = fma2(F1[0], am0, g1);  g2 = fma2(F2[0], am0, g2);
            g1 = fma2(F1[1], am1, g1);  g2 = fma2(F2[1], am1, g2);
            g1 = fma2(F1[2], am2, g1);  g2 = fma2(F2[2], am2, g2);
            g1 = fma2(F1[3], am3, g1);  g2 = fma2(F2[3], am3, g2);
            g1 = fma2(F1[4], am4, g1);  g2 = fma2(F2[4], am4, g2);

            float l1, h1, l2, h2;
            unpk(g1, l1, h1); unpk(g2, l2, h2);

            u64 hp;
            if (j == 0) {
                float ha = (l1 + h1) * (l2 + h2);          // a = 0 (self-mirror; sin lane = 0)
                hp = pk(ha, ha);
            } else {
                float ha = (l1 + h1) * (l2 + h2);          // point a = j
                float hb = (l1 - h1) * (l2 - h2);          // point a = 11 - j
                hp = pk(ha + hb, ha - hb);                 // (sum -> cos lane, diff -> sin lane)
            }
            H[0] = fma2(hp, am0, H[0]);
            H[1] = fma2(hp, am1, H[1]);
            H[2] = fma2(hp, am2, H[2]);
            H[3] = fma2(hp, am3, H[3]);
            H[4] = fma2(hp, am4, H[4]);
        }

        #pragma unroll
        for (int pp = 0; pp < 8; pp++) {
            ulonglong2 Pw2 = Pwv[pp];
            const int p0 = 2 * pp, p1 = 2 * pp + 1;
            accp[p0] = fma2(H[c_m[p0]], Pw2.x, accp[p0]);
            if (p1 < NP) accp[p1] = fma2(H[c_m[p1]], Pw2.y, accp[p1]);
        }
    }

    // ---- output: stage in shared (reuse sBuf), then coalesced float4 stores ----
    __syncthreads();                      // staging fully consumed CTA-wide
    float* sOut = (float*)sBuf;           // 16KB: holds 128*25 floats (12.8KB)
    #pragma unroll
    for (int p = 0; p < NP; p++) {
        float lo, hi; unpk(accp[p], lo, hi);
        sOut[tid * SC + c_ip[p]] = lo;
        if (c_m[p] > 0) sOut[tid * SC + c_in[p]] = hi;
    }
    __syncthreads();
    const float4* sOv = (const float4*)sOut;
    const long long obase4 = (long long)blockIdx.x * TPB * SC / 4;   // CTA tile: 800 float4
    const long long otot4  = (long long)nrows * SC / 4;
    float4* og = (float4*)out;
    #pragma unroll
    for (int k = tid; k < TPB * SC / 4; k += TPB) {
        if (obase4 + k < otot4) og[obase4 + k] = sOv[k];
    }
}

extern "C" void kernel_launch(void* const* d_in, const int* in_sizes, int n_in,
                              void* d_out, int out_size) {
    const float* x1 = (const float*)d_in[0];
    const float* x2 = (const float*)d_in[1];
    const float* W1 = (const float*)d_in[2];
    const float* W2 = (const float*)d_in[3];
    const float* Y  = (const float*)d_in[4];
    const float* Yw = (const float*)d_in[5];
    float* out = (float*)d_out;

    const int nrows = in_sizes[0] / DC;            // 131072
    const int grid  = (nrows + TPB - 1) / TPB;     // 1024

    gtp_main<<<grid, TPB>>>(x1, x2, W1, W2, Y, Yw, out, nrows);
}

// round 11
// speedup vs baseline: 2.2121x; 1.1020x over previous
#include <cuda_runtime.h>

#define SC   25     // (LMAX+1)^2
#define RBC  12
#define RAC  11
#define DC   64
#define NP   15     // (l, m>=0) pairs
#define NQ   10     // m>0 pairs
#define TPB  128

typedef unsigned long long u64;

// ---------- packed f32x2 helpers ----------
__device__ __forceinline__ u64 pk(float lo, float hi) {
    u64 r; asm("mov.b64 %0, {%1,%2};" : "=l"(r) : "f"(lo), "f"(hi)); return r;
}
__device__ __forceinline__ void unpk(u64 v, float& lo, float& hi) {
    asm("mov.b64 {%0,%1}, %2;" : "=f"(lo), "=f"(hi) : "l"(v));
}
__device__ __forceinline__ u64 fma2(u64 a, u64 b, u64 c) {
    u64 d; asm("fma.rn.f32x2 %0, %1, %2, %3;" : "=l"(d) : "l"(a), "l"(b), "l"(c)); return d;
}

// full (l,m) pair tables, p = l(l+1)/2 + m (for acc/output stages, same as R4)
static __device__ const int c_ip[NP] = {0, 2,3, 6,7,8, 12,13,14,15, 20,21,22,23,24};
static __device__ const int c_in[NP] = {0, 2,1, 6,5,4, 12,11,10, 9, 20,19,18,17,16};
static __device__ const int c_m [NP] = {0, 0,1, 0,1,2,  0, 1, 2, 3,  0, 1, 2, 3, 4};

// m=0 subset: s index = l*l+l, l=0..4
static __device__ const int s0_s[5] = {0, 2, 6, 12, 20};
// m>0 subset q=0..9: (l,m) = (1,1),(2,1),(2,2),(3,1),(3,2),(3,3),(4,1),(4,2),(4,3),(4,4)
static __device__ const int q_m [NQ] = {1, 1,2, 1,2,3, 1,2,3,4};
static __device__ const int q_ip[NQ] = {3, 7,8, 13,14,15, 21,22,23,24};
static __device__ const int q_in[NQ] = {1, 5,4, 11,10, 9, 19,18,17,16};

__global__ void __launch_bounds__(TPB, 3)
gtp_main(const float* __restrict__ x1, const float* __restrict__ x2,
         const float* __restrict__ W1, const float* __restrict__ W2,
         const float* __restrict__ Y,  const float* __restrict__ Yw,
         float* __restrict__ out, int nrows)
{
    __shared__ __align__(16) u64 sW0[DC * 8];         // m=0: (W1[d,s], W2[d,s]), slots 0..4; 4KB
    __shared__ __align__(16) ulonglong2 sWpm[DC * NQ];// m>0: {W1(+m,-m), W2(+m,-m)}; 10KB
    __shared__ __align__(16) float4 sBuf[1024];       // input staging, later output staging; 16KB
    __shared__ __align__(16) u64 sP0 [RBC * 8];       // m=0: (P,P) per l
    __shared__ __align__(16) u64 sPpm[RBC * 16];      // m>0: (P,P) per q (+pad)
    __shared__ __align__(16) u64 sPw [RBC * 16];      // full 15: (P*qw, P*qw) (+pad)
    __shared__ __align__(16) u64 sAng[6 * 6];         // alpha half-grid j=0..5: m=0..4 pairs + pad

    const int tid = threadIdx.x;
    const float SQ2  = 1.41421356237309505f;
    const float ISQ2 = 0.70710678118654752f;

    // ---- build tables from W / Y / Yw (exact extraction, no trig) ----
    for (int t = tid; t < DC * 8; t += TPB) {
        int d = t / 8, k = t % 8;
        sW0[t] = (k < 5) ? pk(W1[d * SC + s0_s[k]], W2[d * SC + s0_s[k]]) : 0ull;
    }
    for (int t = tid; t < DC * NQ; t += TPB) {
        int d = t / NQ, q = t % NQ;
        ulonglong2 w;
        w.x = pk(W1[d * SC + q_ip[q]], W1[d * SC + q_in[q]]);
        w.y = pk(W2[d * SC + q_ip[q]], W2[d * SC + q_in[q]]);
        sWpm[t] = w;
    }

    for (int t = tid; t < RBC * 8; t += TPB) {
        int b = t / 8, l = t % 8;
        sP0[t] = (l < 5) ? pk(Y[(b * RAC) * SC + l * l + l], Y[(b * RAC) * SC + l * l + l]) : 0ull;
    }
    for (int t = tid; t < RBC * 16; t += TPB) {
        int b = t / 16, q = t % 16;
        if (q >= NQ) { sPpm[t] = 0ull; }
        else {
            float P = Y[(b * RAC) * SC + q_ip[q]] * ISQ2;   // a=0: ang = sqrt2 for m>0
            sPpm[t] = pk(P, P);
        }
    }
    for (int t = tid; t < RBC * 16; t += TPB) {
        int b = t / 16, p = t % 16;
        if (p == 15) { sPw[t] = 0ull; }
        else {
            int m = c_m[p], ip = c_ip[p];
            float y0 = Y[(b * RAC) * SC + ip];
            float P  = (m > 0) ? y0 * ISQ2 : y0;
            float qw = Yw[(b * RAC) * SC] / Y[(b * RAC) * SC]; // Y[b,0,0] > 0, const over a
            sPw[t] = pk(P * qw, P * qw);
        }
    }

    // alpha half-grid: j=0..5 (points a=6..10 are mirrors of a=5..1)
    for (int t = tid; t < 6 * 6; t += TPB) {
        int a = t / 6, m = t % 6;
        if (m == 5)      sAng[t] = 0ull;
        else if (m == 0) sAng[t] = pk(1.0f, 0.0f);
        else {
            const int b0 = RBC / 2;                            // mid Gauss node, P[m,m] != 0
            int ip = m * m + 2 * m, in_ = m * m;
            float den = Y[(b0 * RAC) * SC + ip];               // sqrt2 * P[m,m](x_b0)
            float ac2 = SQ2 * Y[(b0 * RAC + a) * SC + ip ] / den;
            float as2 = SQ2 * Y[(b0 * RAC + a) * SC + in_] / den;
            sAng[t] = pk(ac2, as2);
        }
    }

    // ---- projection: staged coalesced loads (R4 cadence), mixed packing ----
    u64 cc0[5];                  // (c1[s], c2[s]) for m=0 s-values
    u64 c1p[NQ], c2p[NQ];        // (+m,-m) per input for m>0 pairs
    #pragma unroll
    for (int k = 0; k < 5; k++) cc0[k] = 0ull;
    #pragma unroll
    for (int q = 0; q < NQ; q++) { c1p[q] = 0ull; c2p[q] = 0ull; }

    const long long rowsLeft = (long long)nrows - (long long)blockIdx.x * TPB;
    const long long base = (long long)blockIdx.x * TPB * DC;

    #pragma unroll 1
    for (int qq = 0; qq < 4; qq++) {
        __syncthreads();
        #pragma unroll
        for (int i = 0; i < 4; i++) {
            int k = i * TPB + tid;            // 0..511
            int row = k >> 2, c4 = k & 3;
            long long rg = (row < rowsLeft) ? row : (rowsLeft - 1);
            long long g = base + rg * DC + qq * 16 + c4 * 4;
            int idx = c4 * 128 + ((row + 2 * c4) & 127);   // swizzle: conflict-free STS/LDS
            sBuf[idx]       = *(const float4*)(x1 + g);
            sBuf[512 + idx] = *(const float4*)(x2 + g);
        }
        __syncthreads();
        #pragma unroll
        for (int j = 0; j < 4; j++) {
            int idx = j * 128 + ((tid + 2 * j) & 127);
            float4 A = sBuf[idx];
            float4 B = sBuf[512 + idx];
            float av[4] = {A.x, A.y, A.z, A.w};
            float bv[4] = {B.x, B.y, B.z, B.w};
            #pragma unroll
            for (int w = 0; w < 4; w++) {
                int d = qq * 16 + j * 4 + w;
                u64 xd1  = pk(av[w], av[w]);
                u64 xd2  = pk(bv[w], bv[w]);
                u64 xd12 = pk(av[w], bv[w]);
                const u64* W0 = &sW0[d * 8];
                #pragma unroll
                for (int k = 0; k < 5; k++)
                    cc0[k] = fma2(xd12, W0[k], cc0[k]);
                const ulonglong2* Wq = &sWpm[d * NQ];
                #pragma unroll
                for (int q = 0; q < NQ; q++) {
                    ulonglong2 W = Wq[q];
                    c1p[q] = fma2(xd1, W.x, c1p[q]);
                    c2p[q] = fma2(xd2, W.y, c2p[q]);
                }
            }
        }
    }

    // ---- sphere: per beta node, F -> mirrored alpha grid -> H -> back-project ----
    u64 accp[NP];
    #pragma unroll
    for (int p = 0; p < NP; p++) accp[p] = 0ull;

    #pragma unroll 1
    for (int b = 0; b < RBC; b++) {
        const u64* P0v = &sP0[b * 8];
        const ulonglong2* Pqv = (const ulonglong2*)&sPpm[b * 16];
        const ulonglong2* Pwv = (const ulonglong2*)&sPw [b * 16];

        // m=0: F0 = (F1_0, F2_0) = sum_l cc0[l] * P[l,0]
        u64 F0 = 0ull;
        #pragma unroll
        for (int l = 0; l < 5; l++) F0 = fma2(cc0[l], P0v[l], F0);
        float f1, f2; unpk(F0, f1, f2);
        u64 g1_0 = pk(f1, 0.0f), g2_0 = pk(f2, 0.0f);

        // m>0: F1[m-1], F2[m-1] with (+m,-m) lanes
        u64 F1[4], F2[4];
        #pragma unroll
        for (int m = 0; m < 4; m++) { F1[m] = 0ull; F2[m] = 0ull; }
        #pragma unroll
        for (int qq2 = 0; qq2 < 5; qq2++) {
            ulonglong2 P2 = Pqv[qq2];
            const int q0 = 2 * qq2, q1 = 2 * qq2 + 1;
            F1[q_m[q0] - 1] = fma2(c1p[q0], P2.x, F1[q_m[q0] - 1]);
            F2[q_m[q0] - 1] = fma2(c2p[q0], P2.x, F2[q_m[q0] - 1]);
            F1[q_m[q1] - 1] = fma2(c1p[q1], P2.y, F1[q_m[q1] - 1]);
            F2[q_m[q1] - 1] = fma2(c2p[q1], P2.y, F2[q_m[q1] - 1]);
        }

        u64 H[5];
        #pragma unroll
        for (int m = 0; m < 5; m++) H[m] = 0ull;

        // alpha half-grid: chain lanes = (cos-part, sin-part); g(a)=lo+hi, g(11-a)=lo-hi
        #pragma unroll
        for (int j = 0; j < 6; j++) {
            const ulonglong2* Av = (const ulonglong2*)&sAng[j * 6];
            ulonglong2 A0 = Av[0], A1 = Av[1], A2 = Av[2];
            u64 am0 = A0.x, am1 = A0.y, am2 = A1.x, am3 = A1.y, am4 = A2.x;

            u64 g1 = g1_0, g2 = g2_0;               // m=0 seed (loop-invariant)
            g1 = fma2(F1[0], am1, g1);  g2 = fma2(F2[0], am1, g2);
            g1 = fma2(F1[1], am2, g1);  g2 = fma2(F2[1], am2, g2);
            g1 = fma2(F1[2], am3, g1);  g2 = fma2(F2[2], am3, g2);
            g1 = fma2(F1[3], am4, g1);  g2 = fma2(F2[3], am4, g2);

            float l1, h1, l2, h2;
            unpk(g1, l1, h1); unpk(g2, l2, h2);

            u64 hp;
            if (j == 0) {
                float ha = (l1 + h1) * (l2 + h2);          // a = 0 (self-mirror; sin lane = 0)
                hp = pk(ha, ha);
            } else {
                float ha = (l1 + h1) * (l2 + h2);          // point a = j
                float hb = (l1 - h1) * (l2 - h2);          // point a = 11 - j
                hp = pk(ha + hb, ha - hb);                 // (sum -> cos lane, diff -> sin lane)
            }
            H[0] = fma2(hp, am0, H[0]);
            H[1] = fma2(hp, am1, H[1]);
            H[2] = fma2(hp, am2, H[2]);
            H[3] = fma2(hp, am3, H[3]);
            H[4] = fma2(hp, am4, H[4]);
        }

        #pragma unroll
        for (int pp = 0; pp < 8; pp++) {
            ulonglong2 Pw2 = Pwv[pp];
            const int p0 = 2 * pp, p1 = 2 * pp + 1;
            accp[p0] = fma2(H[c_m[p0]], Pw2.x, accp[p0]);
            if (p1 < NP) accp[p1] = fma2(H[c_m[p1]], Pw2.y, accp[p1]);
        }
    }

    // ---- output: stage in shared (reuse sBuf), then coalesced float4 stores ----
    __syncthreads();                      // sBuf dead as input staging everywhere in CTA
    float* sOut = (float*)sBuf;
    #pragma unroll
    for (int p = 0; p < NP; p++) {
        float lo, hi; unpk(accp[p], lo, hi);
        sOut[tid * SC + c_ip[p]] = lo;
        if (c_m[p] > 0) sOut[tid * SC + c_in[p]] = hi;
    }
    __syncthreads();
    const float4* sOv = (const float4*)sOut;
    const long long obase4 = (long long)blockIdx.x * TPB * SC / 4;   // CTA tile: 800 float4
    const long long otot4  = (long long)nrows * SC / 4;
    float4* og = (float4*)out;
    #pragma unroll
    for (int k = tid; k < TPB * SC / 4; k += TPB) {
        if (obase4 + k < otot4) og[obase4 + k] = sOv[k];
    }
}

extern "C" void kernel_launch(void* const* d_in, const int* in_sizes, int n_in,
                              void* d_out, int out_size) {
    const float* x1 = (const float*)d_in[0];
    const float* x2 = (const float*)d_in[1];
    const float* W1 = (const float*)d_in[2];
    const float* W2 = (const float*)d_in[3];
    const float* Y  = (const float*)d_in[4];
    const float* Yw = (const float*)d_in[5];
    float* out = (float*)d_out;

    const int nrows = in_sizes[0] / DC;            // 131072
    const int grid  = (nrows + TPB - 1) / TPB;     // 1024

    gtp_main<<<grid, TPB>>>(x1, x2, W1, W2, Y, Yw, out, nrows);
}